// round 9
// baseline (speedup 1.0000x reference)
#include <cuda_runtime.h>
#include <cuda_fp16.h>
#include <cstdint>
#include <cstddef>

// ================= problem =================
// x:(16,128,112,112)f32  weight:(128,128,3,3)  P:(2,128,128,3,3)  bias:(128)
// out:(16,128,112,112) = conv(x, scatter(weight,P) 9x9, pad 4) + bias

#define TAPS 81

// K2 fragment layout: [tap][ci16(8)][cotile16(8)][lane(32)] uint4 (2048 uint4/tap).
// Lane's uint4 = m16k16 fp16 A-frag regs {a0,a1,a2,a3}:
//   lane=(row&7)*4+((col&7)>>1), reg=(row>>3)+((col>>3)<<1), half=(col&1)
__device__ uint4 g_K2f[TAPS * 8 * 8 * 32];

// x transposed to f16 NHWC with halo: [b][h+4 (120)][w+4 (120)][ci (128)]
#define XT_U4 (16 * 120 * 120 * 128 / 8)      // 3,686,400 uint4
__device__ uint4 g_xT[XT_U4];

__device__ __forceinline__ uint32_t smem_u32(const void* p) {
    uint32_t a;
    asm("{ .reg .u64 t; cvta.to.shared.u64 t, %1; cvt.u32.u64 %0, t; }" : "=r"(a) : "l"(p));
    return a;
}

#define LDSM4(rv, addr)                                                          \
    asm volatile("ldmatrix.sync.aligned.m8n8.x4.shared.b16 {%0,%1,%2,%3}, [%4];" \
        : "=r"((rv)[0]), "=r"((rv)[1]), "=r"((rv)[2]), "=r"((rv)[3]) : "r"(addr))

#define LDSM2(rv, addr)                                                      \
    asm volatile("ldmatrix.sync.aligned.m8n8.x2.shared.b16 {%0,%1}, [%2];"   \
        : "=r"((rv)[0]), "=r"((rv)[1]) : "r"(addr))

#define HMMA(d, a, b0, b1)                                                   \
    asm volatile("mma.sync.aligned.m16n8k16.row.col.f32.f16.f16.f32 "        \
        "{%0,%1,%2,%3}, {%4,%5,%6,%7}, {%8,%9}, {%0,%1,%2,%3};"              \
        : "+f"((d)[0]), "+f"((d)[1]), "+f"((d)[2]), "+f"((d)[3])             \
        : "r"((a)[0]), "r"((a)[1]), "r"((a)[2]), "r"((a)[3]),                \
          "r"(b0), "r"(b1))

#define CP_ASYNC16(sdst, gsrc)                                               \
    asm volatile("cp.async.cg.shared.global [%0], [%1], 16;"                 \
        :: "r"(sdst), "l"(gsrc) : "memory")
#define CP_COMMIT()   asm volatile("cp.async.commit_group;" ::: "memory")
#define CP_WAIT0()    asm volatile("cp.async.wait_group 0;" ::: "memory")
#define CP_WAIT1()    asm volatile("cp.async.wait_group 1;" ::: "memory")

// ================= pre-pass A: zero-fill xT (halo stays zero) =================
__global__ void fill_xT() {
    g_xT[blockIdx.x * 256 + threadIdx.x] = make_uint4(0, 0, 0, 0);
}

// ================= pre-pass B: transpose x -> f16 NHWC interior =================
// block = (b, h) : 16*112 blocks, 256 threads. smem tile [w][ci].
__global__ void transpose_xT(const float* __restrict__ x) {
    __shared__ __half s[112 * 130];
    const int b = blockIdx.x >> 7;        // grid = 16*128? no: use y
    const int hh = blockIdx.x & 127;      // 0..111 valid (grid x = 16*128 padded)
    if (hh >= 112) return;
    const int tid = threadIdx.x;

    const float* xb = x + ((size_t)b * 128) * 12544 + hh * 112;
    for (int u = tid; u < 128 * 112; u += 256) {
        int ci = u / 112, w = u - ci * 112;
        s[w * 130 + ci] = __float2half_rn(xb[(size_t)ci * 12544 + w]);
    }
    __syncthreads();

    __half* xt = (__half*)g_xT + (((size_t)b * 120 + (hh + 4)) * 120 + 4) * 128;
    for (int u = tid; u < 112 * 64; u += 256) {
        int w = u >> 6, cp = u & 63;
        __half2 v = make_half2(s[w * 130 + 2 * cp], s[w * 130 + 2 * cp + 1]);
        *(__half2*)(xt + (size_t)w * 128 + 2 * cp) = v;
    }
}

// ================= stage 1: scatter weights -> fragment-layout f16 K2 =================
__global__ void build_K(const float* __restrict__ weight, const float* __restrict__ P) {
    __shared__ float sK[128][81];
    const int co = blockIdx.x;
    const int ci = threadIdx.x;

    #pragma unroll
    for (int i = 0; i < 81; i++) sK[ci][i] = 0.f;

    const float* P0 = P;
    const float* P1 = P + 128 * 128 * 9;

    #pragma unroll
    for (int kh = 0; kh < 3; kh++) {
        #pragma unroll
        for (int kw = 0; kw < 3; kw++) {
            int widx = ((co * 128 + ci) * 3 + kh) * 3 + kw;
            float w  = weight[widx];
            float ph = (float)(kh * 4) + P0[widx];
            float pw = (float)(kw * 4) + P1[widx];
            ph = fminf(fmaxf(ph, 0.f), 8.f);
            pw = fminf(fmaxf(pw, 0.f), 8.f);
            float fh = floorf(ph), fw = floorf(pw);
            float rh = ph - fh,    rw = pw - fw;
            int ih = (int)fh, iw = (int)fw;
            int ih1 = min(ih + 1, 8), iw1 = min(iw + 1, 8);
            sK[ci][ih  * 9 + iw ] += w * (1.f - rh) * (1.f - rw);
            sK[ci][ih1 * 9 + iw ] += w * rh         * (1.f - rw);
            sK[ci][ih  * 9 + iw1] += w * (1.f - rh) * rw;
            sK[ci][ih1 * 9 + iw1] += w * rh         * rw;
        }
    }
    __syncwarp();

    // (co,ci) -> fragment slot  (ci16 chunks)
    const int c8   = ci >> 4;
    const int col  = ci & 15;
    const int ig   = co >> 4;
    const int row  = co & 15;
    const int lane = (row & 7) * 4 + ((col & 7) >> 1);
    const int reg  = (row >> 3) + ((col >> 3) << 1);
    __half* gh = (__half*)g_K2f;
    const size_t slot = (((size_t)c8 * 8 + ig) * 32 + lane) * 8 + reg * 2 + (col & 1);
    for (int tap = 0; tap < 81; tap++)
        gh[(size_t)tap * 16384 + slot] = __float2half_rn(sK[ci][tap]);
}

// ================= stage 2: fp16 implicit-GEMM conv =================
// Block (128 thr, occ 2): 64 co x (4 rows x 56 w). 4 warps = 4 rows.
// Warp tile: 64co x 56px = 4 m-frags x 7 n-frags (112 acc regs).
// K = ci in 8 chunks of 16 (one m16n8k16 step each).
// A: fragment-layout LDG, register double-buffered.
// B: x tile (12 rows x 64 cols x 16 ci) via cp.async from f16 NHWC xT,
//    double-buffered in smem; chunk c+2 staged while computing chunk c.
#define XS_STRIDE 48
#define XS_BUF    (768 * XS_STRIDE)       // 36864 B
#define SMEM_TOTAL (2 * XS_BUF)           // 73728 B

__global__ __launch_bounds__(128, 2)
void dcls_mma(const float* __restrict__ bias, float* __restrict__ out) {
    extern __shared__ char smem[];
    const uint32_t sb = smem_u32(smem);

    const int tid  = threadIdx.x;
    const int lane = tid & 31;
    const int r    = tid >> 5;       // warp = output row 0..3

    const int s  = blockIdx.x;       // 0..1791
    const int h  = s & 1;            // co half
    const int wt = (s >> 1) & 1;
    const int hg = (s >> 2) % 28;
    const int bb = s / 112;
    const int h0 = hg * 4;
    const int w0 = wt * 56;
    const int co0 = h * 64;

    // ldmatrix B lane offset (16 rows stride 48: conflict-free, offsets mod 128
    // cycle through all eight 16B segments)
    const int bnrow = (lane & 7) + ((lane >> 4) << 3);
    const uint32_t b_lane = (uint32_t)(bnrow * XS_STRIDE + ((lane >> 3) & 1) * 16);

    const char* xtb = (const char*)g_xT + ((size_t)bb * 120 * 120) * 256;

    float acc[4][7][4];
    #pragma unroll
    for (int i = 0; i < 4; i++)
        #pragma unroll
        for (int j = 0; j < 7; j++)
            #pragma unroll
            for (int k = 0; k < 4; k++) acc[i][j][k] = 0.f;

    // ---- stage chunk c into buffer c&1 (12 cp.async.16 per thread) ----
    #define STAGE(c) do {                                                        \
        const uint32_t dstb = sb + ((c) & 1) * XS_BUF;                           \
        _Pragma("unroll")                                                        \
        for (int i_ = 0; i_ < 6; i_++) {                                         \
            int u   = tid + i_ * 128;          /* 0..767: pixel */               \
            int hp  = h0 + (u >> 6);                                             \
            int wp  = w0 + (u & 63);                                             \
            const char* src = xtb + ((size_t)(hp * 120 + wp) << 8) + (c) * 32;   \
            uint32_t dst = dstb + u * XS_STRIDE;                                 \
            CP_ASYNC16(dst,      src);                                           \
            CP_ASYNC16(dst + 16, src + 16);                                      \
        }                                                                        \
        CP_COMMIT();                                                             \
    } while (0)

    STAGE(0);
    STAGE(1);

    for (int c = 0; c < 8; c++) {
        // first A frags of this chunk (global, no smem dependency)
        const uint4* Ac = g_K2f + (size_t)c * 256 + (h * 4) * 32 + lane;
        uint4 cur[4], nxt[4];
        #pragma unroll
        for (int i = 0; i < 4; i++) cur[i] = Ac[i * 32];

        if (c == 7) { CP_WAIT0(); } else { CP_WAIT1(); }   // chunk c's data landed
        __syncthreads();

        const uint32_t xbb = sb + (c & 1) * XS_BUF;
        int dh = 0, dw = 0;
        for (int tap = 0; tap < 81; tap++) {
            if (tap < 80) {
                const uint4* An = Ac + (size_t)(tap + 1) * 2048;
                #pragma unroll
                for (int i = 0; i < 4; i++) nxt[i] = An[i * 32];
            }

            const uint32_t bbase = xbb + (uint32_t)(((r + dh) * 64 + dw) * XS_STRIDE) + b_lane;

            #pragma unroll
            for (int j2 = 0; j2 < 3; j2++) {
                uint32_t b[4];
                LDSM4(b, bbase + j2 * (16 * XS_STRIDE));
                #pragma unroll
                for (int i = 0; i < 4; i++) {
                    const uint32_t* a = reinterpret_cast<const uint32_t*>(&cur[i]);
                    HMMA(acc[i][2 * j2],     a, b[0], b[1]);
                    HMMA(acc[i][2 * j2 + 1], a, b[2], b[3]);
                }
            }
            {
                uint32_t b2[2];
                LDSM2(b2, bbase + 3 * (16 * XS_STRIDE));
                #pragma unroll
                for (int i = 0; i < 4; i++) {
                    const uint32_t* a = reinterpret_cast<const uint32_t*>(&cur[i]);
                    HMMA(acc[i][6], a, b2[0], b2[1]);
                }
            }

            if (tap < 80) {
                #pragma unroll
                for (int i = 0; i < 4; i++) cur[i] = nxt[i];
            }
            if (++dw == 9) { dw = 0; dh++; }
        }

        __syncthreads();               // all warps done reading buffer c&1
        if (c + 2 < 8) STAGE(c + 2);   // reuse it for chunk c+2
    }

    // ================= epilogue: + bias, float2 stores =================
    const int gq = lane >> 2, tq = lane & 3;
    #pragma unroll
    for (int i = 0; i < 4; i++) {
        const int co = co0 + i * 16 + gq;
        const float b0 = bias[co];
        const float b1 = bias[co + 8];
        const size_t o0 = ((size_t)(bb * 128 + co) * 112 + (h0 + r)) * 112 + w0;
        const size_t o1 = o0 + (size_t)8 * 12544;
        #pragma unroll
        for (int j = 0; j < 7; j++) {
            const int wcol = j * 8 + tq * 2;
            *(float2*)(out + o0 + wcol) = make_float2(acc[i][j][0] + b0, acc[i][j][1] + b0);
            *(float2*)(out + o1 + wcol) = make_float2(acc[i][j][2] + b1, acc[i][j][3] + b1);
        }
    }
}

// ================= launch =================
extern "C" void kernel_launch(void* const* d_in, const int* in_sizes, int n_in,
                              void* d_out, int out_size) {
    const float* x      = (const float*)d_in[0];
    const float* weight = (const float*)d_in[1];
    const float* P      = (const float*)d_in[2];
    const float* bias   = (const float*)d_in[3];
    float* out = (float*)d_out;

    fill_xT<<<XT_U4 / 256, 256>>>();
    transpose_xT<<<16 * 128, 256>>>(x);
    build_K<<<128, 128>>>(weight, P);

    cudaFuncSetAttribute(dcls_mma, cudaFuncAttributeMaxDynamicSharedMemorySize, SMEM_TOTAL);
    dcls_mma<<<1792, 128, SMEM_TOTAL>>>(bias, out);
}

// round 10
// speedup vs baseline: 1.2534x; 1.2534x over previous
#include <cuda_runtime.h>
#include <cuda_fp16.h>
#include <cstdint>
#include <cstddef>

// ================= problem =================
// x:(16,128,112,112)f32  weight:(128,128,3,3)  P:(2,128,128,3,3)  bias:(128)
// out:(16,128,112,112) = conv(x, scatter(weight,P) 9x9, pad 4) + bias

#define TAPS 81

// K2 fragment layout: [tap][cichunk(4)][cotile16(8)][kk(2)][lane(32)] uint4
// (2048 uint4 / tap). Lane's uint4 = m16k16 fp16 A-frag regs {a0,a1,a2,a3}:
//   lane=(row&7)*4+((col&7)>>1), reg=(row>>3)+((col>>3)<<1), half=(col&1)
__device__ uint4 g_K2f[TAPS * 4 * 8 * 2 * 32];

// x transposed to f16 NHWC with baked-in halo: [b][h+4 (120)][w+4 (120)][ci 128]
#define XT_U4 (16 * 120 * 120 * 128 / 8)      // 3,686,400 uint4
__device__ uint4 g_xT[XT_U4];

__device__ __forceinline__ uint32_t smem_u32(const void* p) {
    uint32_t a;
    asm("{ .reg .u64 t; cvta.to.shared.u64 t, %1; cvt.u32.u64 %0, t; }" : "=r"(a) : "l"(p));
    return a;
}

#define LDSM4(rv, addr)                                                          \
    asm volatile("ldmatrix.sync.aligned.m8n8.x4.shared.b16 {%0,%1,%2,%3}, [%4];" \
        : "=r"((rv)[0]), "=r"((rv)[1]), "=r"((rv)[2]), "=r"((rv)[3]) : "r"(addr))

#define LDSM2(rv, addr)                                                      \
    asm volatile("ldmatrix.sync.aligned.m8n8.x2.shared.b16 {%0,%1}, [%2];"   \
        : "=r"((rv)[0]), "=r"((rv)[1]) : "r"(addr))

#define HMMA(d, a, b0, b1)                                                   \
    asm volatile("mma.sync.aligned.m16n8k16.row.col.f32.f16.f16.f32 "        \
        "{%0,%1,%2,%3}, {%4,%5,%6,%7}, {%8,%9}, {%0,%1,%2,%3};"              \
        : "+f"((d)[0]), "+f"((d)[1]), "+f"((d)[2]), "+f"((d)[3])             \
        : "r"((a)[0]), "r"((a)[1]), "r"((a)[2]), "r"((a)[3]),                \
          "r"(b0), "r"(b1))

#define CP_ASYNC16(sdst, gsrc)                                               \
    asm volatile("cp.async.cg.shared.global [%0], [%1], 16;"                 \
        :: "r"(sdst), "l"(gsrc) : "memory")
#define CP_COMMIT()   asm volatile("cp.async.commit_group;" ::: "memory")
#define CP_WAIT0()    asm volatile("cp.async.wait_group 0;" ::: "memory")

// ================= pre-pass A: zero-fill xT (halo stays zero) =================
__global__ void fill_xT() {
    g_xT[blockIdx.x * 256 + threadIdx.x] = make_uint4(0, 0, 0, 0);
}

// ================= pre-pass B: transpose x -> f16 NHWC interior =================
__global__ void transpose_xT(const float* __restrict__ x) {
    __shared__ __half s[112 * 130];
    const int b  = blockIdx.x >> 7;
    const int hh = blockIdx.x & 127;
    if (hh >= 112) return;
    const int tid = threadIdx.x;

    const float* xb = x + ((size_t)b * 128) * 12544 + hh * 112;
    for (int u = tid; u < 128 * 112; u += 256) {
        int ci = u / 112, w = u - ci * 112;
        s[w * 130 + ci] = __float2half_rn(xb[(size_t)ci * 12544 + w]);
    }
    __syncthreads();

    __half* xt = (__half*)g_xT + (((size_t)b * 120 + (hh + 4)) * 120 + 4) * 128;
    for (int u = tid; u < 112 * 64; u += 256) {
        int w = u >> 6, cp = u & 63;
        __half2 v = make_half2(s[w * 130 + 2 * cp], s[w * 130 + 2 * cp + 1]);
        *(__half2*)(xt + (size_t)w * 128 + 2 * cp) = v;
    }
}

// ================= stage 1: scatter weights -> fragment-layout f16 K2 =================
__global__ void build_K(const float* __restrict__ weight, const float* __restrict__ P) {
    __shared__ float sK[128][81];
    const int co = blockIdx.x;
    const int ci = threadIdx.x;

    #pragma unroll
    for (int i = 0; i < 81; i++) sK[ci][i] = 0.f;

    const float* P0 = P;
    const float* P1 = P + 128 * 128 * 9;

    #pragma unroll
    for (int kh = 0; kh < 3; kh++) {
        #pragma unroll
        for (int kw = 0; kw < 3; kw++) {
            int widx = ((co * 128 + ci) * 3 + kh) * 3 + kw;
            float w  = weight[widx];
            float ph = (float)(kh * 4) + P0[widx];
            float pw = (float)(kw * 4) + P1[widx];
            ph = fminf(fmaxf(ph, 0.f), 8.f);
            pw = fminf(fmaxf(pw, 0.f), 8.f);
            float fh = floorf(ph), fw = floorf(pw);
            float rh = ph - fh,    rw = pw - fw;
            int ih = (int)fh, iw = (int)fw;
            int ih1 = min(ih + 1, 8), iw1 = min(iw + 1, 8);
            sK[ci][ih  * 9 + iw ] += w * (1.f - rh) * (1.f - rw);
            sK[ci][ih1 * 9 + iw ] += w * rh         * (1.f - rw);
            sK[ci][ih  * 9 + iw1] += w * (1.f - rh) * rw;
            sK[ci][ih1 * 9 + iw1] += w * rh         * rw;
        }
    }
    __syncwarp();

    // (co,ci) -> fragment slot (k32 chunks: cichunk = ci>>5, kk = (ci>>4)&1)
    const int c     = ci >> 5;
    const int kk    = (ci >> 4) & 1;
    const int col   = ci & 15;
    const int iglob = co >> 4;
    const int row   = co & 15;
    const int lane  = (row & 7) * 4 + ((col & 7) >> 1);
    const int reg   = (row >> 3) + ((col >> 3) << 1);
    __half* gh = (__half*)g_K2f;
    const size_t slot = ((((size_t)c * 8 + iglob) * 2 + kk) * 32 + lane) * 8 + reg * 2 + (col & 1);
    for (int tap = 0; tap < 81; tap++)
        gh[(size_t)tap * 16384 + slot] = __float2half_rn(sK[ci][tap]);
}

// ================= stage 2: fp16 implicit-GEMM conv =================
// Round-6 compute structure (proven 77.9% tensor):
//   Block: 128 co x (4 rows x 56 w). 8 warps = 2 co-halves(64) x 4 rows.
//   Warp tile: 64co x 56px = 4 m-frags x 7 n-frags. K = ci, 4 chunks of 32.
//   A: fragment-layout LDG, register double-buffered (448-cyc MMA chain
//      per tap covers L2 latency).
// New: B x-tile staged via cp.async.16 from f16 NHWC xT, DOUBLE-BUFFERED:
//   chunk c+1 streams in under chunk c's compute. 1 barrier per chunk.
#define XS_STRIDE 80
#define XS_BUF    (768 * XS_STRIDE)       // 12 rows x 64 cols pixels = 61440 B
#define SMEM_TOTAL (2 * XS_BUF)           // 122880 B

__global__ __launch_bounds__(256, 1)
void dcls_mma(const float* __restrict__ bias, float* __restrict__ out) {
    extern __shared__ char smem[];
    const uint32_t sb = smem_u32(smem);

    const int tid  = threadIdx.x;
    const int lane = tid & 31;
    const int warp = tid >> 5;
    const int h    = warp & 1;       // co half (64) within block
    const int r    = warp >> 1;      // output row 0..3

    const int s  = blockIdx.x;       // 0..895
    const int wt = s & 1;
    const int hg = (s >> 1) % 28;
    const int bb = s / 56;
    const int h0 = hg * 4;
    const int w0 = wt * 56;

    // ldmatrix B lane offset
    const int bnrow = (lane & 7) + ((lane >> 4) << 3);
    const uint32_t b_lane = (uint32_t)(bnrow * XS_STRIDE + ((lane >> 3) & 1) * 16);

    const char* xtb = (const char*)g_xT + ((size_t)bb * 120 * 120) * 256;

    float acc[4][7][4];
    #pragma unroll
    for (int i = 0; i < 4; i++)
        #pragma unroll
        for (int j = 0; j < 7; j++)
            #pragma unroll
            for (int k = 0; k < 4; k++) acc[i][j][k] = 0.f;

    // stage x chunk c (32 ci = 64 B/pixel) into buffer c&1: 12 cp.async/thread
    #define STAGE(c) do {                                                        \
        const uint32_t dstb = sb + ((c) & 1) * XS_BUF;                           \
        _Pragma("unroll")                                                        \
        for (int i_ = 0; i_ < 3; i_++) {                                         \
            int u  = tid + i_ * 256;           /* pixel 0..767 */                \
            int hp = h0 + (u >> 6);                                              \
            int wp = w0 + (u & 63);                                              \
            const char* src = xtb + ((size_t)(hp * 120 + wp) << 8) + (c) * 64;   \
            uint32_t dst = dstb + u * XS_STRIDE;                                 \
            CP_ASYNC16(dst,      src);                                           \
            CP_ASYNC16(dst + 16, src + 16);                                      \
            CP_ASYNC16(dst + 32, src + 32);                                      \
            CP_ASYNC16(dst + 48, src + 48);                                      \
        }                                                                        \
        CP_COMMIT();                                                             \
    } while (0)

    STAGE(0);

    for (int c = 0; c < 4; c++) {
        // first A frags of this chunk (pure global, overlaps the wait)
        const uint4* Ab = g_K2f + ((size_t)c * 16 + h * 8) * 32 + lane;
        uint4 cur[8], nxt[8];
        #pragma unroll
        for (int t = 0; t < 8; t++) cur[t] = Ab[t * 32];

        CP_WAIT0();          // chunk c's x tile landed
        __syncthreads();     // ... and previous chunk's readers are done
        if (c < 3) STAGE(c + 1);   // stream next chunk under this compute

        const uint32_t xbb = sb + (c & 1) * XS_BUF;
        int dh = 0, dw = 0;
        for (int tap = 0; tap < 81; tap++) {
            if (tap < 80) {
                const uint4* An = Ab + (size_t)(tap + 1) * 2048;
                #pragma unroll
                for (int t = 0; t < 8; t++) nxt[t] = An[t * 32];
            }

            const uint32_t bbase = xbb + (uint32_t)(((r + dh) * 64 + dw) * XS_STRIDE) + b_lane;

            #pragma unroll
            for (int kk = 0; kk < 2; kk++) {
                #pragma unroll
                for (int j2 = 0; j2 < 3; j2++) {
                    uint32_t b[4];
                    LDSM4(b, bbase + j2 * 1280 + kk * 32);
                    #pragma unroll
                    for (int i = 0; i < 4; i++) {
                        const uint32_t* a = reinterpret_cast<const uint32_t*>(&cur[i * 2 + kk]);
                        HMMA(acc[i][2 * j2],     a, b[0], b[1]);
                        HMMA(acc[i][2 * j2 + 1], a, b[2], b[3]);
                    }
                }
                uint32_t b2[2];
                LDSM2(b2, bbase + 3 * 1280 + kk * 32);
                #pragma unroll
                for (int i = 0; i < 4; i++) {
                    const uint32_t* a = reinterpret_cast<const uint32_t*>(&cur[i * 2 + kk]);
                    HMMA(acc[i][6], a, b2[0], b2[1]);
                }
            }

            if (tap < 80) {
                #pragma unroll
                for (int t = 0; t < 8; t++) cur[t] = nxt[t];
            }
            if (++dw == 9) { dw = 0; dh++; }
        }
    }

    // ================= epilogue: + bias, float2 stores =================
    const int gq = lane >> 2, tq = lane & 3;
    #pragma unroll
    for (int i = 0; i < 4; i++) {
        const int co = h * 64 + i * 16 + gq;
        const float b0 = bias[co];
        const float b1 = bias[co + 8];
        const size_t o0 = ((size_t)(bb * 128 + co) * 112 + (h0 + r)) * 112 + w0;
        const size_t o1 = o0 + (size_t)8 * 12544;
        #pragma unroll
        for (int j = 0; j < 7; j++) {
            const int wcol = j * 8 + tq * 2;
            *(float2*)(out + o0 + wcol) = make_float2(acc[i][j][0] + b0, acc[i][j][1] + b0);
            *(float2*)(out + o1 + wcol) = make_float2(acc[i][j][2] + b1, acc[i][j][3] + b1);
        }
    }
}

// ================= launch =================
extern "C" void kernel_launch(void* const* d_in, const int* in_sizes, int n_in,
                              void* d_out, int out_size) {
    const float* x      = (const float*)d_in[0];
    const float* weight = (const float*)d_in[1];
    const float* P      = (const float*)d_in[2];
    const float* bias   = (const float*)d_in[3];
    float* out = (float*)d_out;

    fill_xT<<<XT_U4 / 256, 256>>>();
    transpose_xT<<<16 * 128, 256>>>(x);
    build_K<<<128, 128>>>(weight, P);

    cudaFuncSetAttribute(dcls_mma, cudaFuncAttributeMaxDynamicSharedMemorySize, SMEM_TOTAL);
    dcls_mma<<<896, 256, SMEM_TOTAL>>>(bias, out);
}